// round 16
// baseline (speedup 1.0000x reference)
#include <cuda_runtime.h>
#include <cuda_fp16.h>
#include <math.h>

#define H 64
#define W 64
#define C 256
#define P 7
#define NUM_ROIS 256
#define NBINS (NUM_ROIS * P * P)   // 12544
#define FC (W * C)                 // floats per x-row
#define RS8 (FC / 8)               // x-row stride in uint4 (8-half) units: 2048
#define CS8 (C / 8)                // y-col stride in uint4 units: 32

// fp16 feature map (2 MB), 16B-aligned via uint4
__device__ uint4 g_f16raw[H * W * C / 8];
__device__ int   g_nflag;
__device__ int   g_flags[NBINS];

__device__ __forceinline__ __half2 u2h(unsigned u) { return *reinterpret_cast<__half2*>(&u); }
__device__ __forceinline__ unsigned h2u(__half2 h) { return *reinterpret_cast<unsigned*>(&h); }
__device__ __forceinline__ unsigned hmax2u(unsigned a, unsigned b) {
    return h2u(__hmax2(u2h(a), u2h(b)));
}
__device__ __forceinline__ uint4 hmax4(uint4 a, uint4 b) {
    a.x = hmax2u(a.x, b.x); a.y = hmax2u(a.y, b.y);
    a.z = hmax2u(a.z, b.z); a.w = hmax2u(a.w, b.w);
    return a;
}
__device__ __forceinline__ float4 fmax4f(float4 a, float4 b) {
    a.x = fmaxf(a.x, b.x); a.y = fmaxf(a.y, b.y);
    a.z = fmaxf(a.z, b.z); a.w = fmaxf(a.w, b.w);
    return a;
}

// exact reference bin math (shared)
__device__ __forceinline__ void bin_bounds(float lo_f, float hi_f, int k,
                                           int& start, int& len) {
    const int lo   = (int)floorf(lo_f * 64.0f);
    const int hi   = (int)ceilf(hi_f * 64.0f);
    const int span = max(hi - lo, 1);
    int s          = lo + (k * span) / P;
    const int e    = lo + ((k + 1) * span + (P - 1)) / P;
    len = max(e - s, 1);
    start = min(max(s, 0), 63);
}

// K1: fp32 -> fp16 feature map; also resets flag counter.
__global__ __launch_bounds__(256) void convert_kernel(const float* __restrict__ feat) {
    const int i = blockIdx.x * 256 + (int)threadIdx.x;   // uint4 (8-half) index
    if (i == 0) g_nflag = 0;
    const float4* f4 = reinterpret_cast<const float4*>(feat);
    const float4 a = f4[i * 2];
    const float4 b = f4[i * 2 + 1];
    uint4 o;
    o.x = h2u(__floats2half2_rn(a.x, a.y));
    o.y = h2u(__floats2half2_rn(a.z, a.w));
    o.z = h2u(__floats2half2_rn(b.x, b.y));
    o.w = h2u(__floats2half2_rn(b.z, b.w));
    g_f16raw[i] = o;
}

// K2: hot pool. 1568 CTAs x 256 thr = 8 warps; warp = one bin.
// Lane covers channels [8*lane, 8*lane+8) -> ONE 16B load per tap covers all C.
// Tap grids (batched; clamp-dups are same-address L1 hits, max-safe).
// Warps holding any |max| < 1e-4 (possible fp16-subnormal hazard) enqueue their
// bin for exact fp32 fixup.
__global__ __launch_bounds__(256) void roi_pool_kernel(
    const float* __restrict__ rois,
    float* __restrict__ out)          // (NBINS, C)
{
    const int bin  = blockIdx.x * 8 + ((int)threadIdx.x >> 5);
    const int lane = (int)threadIdx.x & 31;

    const int r  = bin / (P * P);
    const int ij = bin - r * (P * P);
    const int i  = ij / P;
    const int j  = ij - i * P;

    int xs, xlen, ys, ylen;
    bin_bounds(__ldg(&rois[r * 4 + 0]), __ldg(&rois[r * 4 + 2]), i, xs, xlen);
    bin_bounds(__ldg(&rois[r * 4 + 1]), __ldg(&rois[r * 4 + 3]), j, ys, ylen);

    const int xm = xlen - 1;
    const int ym = ylen - 1;
    const uint4* pb = g_f16raw + (size_t)xs * RS8 + (size_t)ys * CS8 + lane;
    const int co1 = min(1, ym) * CS8;

    const unsigned NEGU = 0xFC00FC00u;   // half2(-inf, -inf)
    uint4 acc = make_uint4(NEGU, NEGU, NEGU, NEGU);

    if (xlen <= 2 && ylen <= 2) {
        const uint4* r1 = pb + (size_t)min(1, xm) * RS8;
        const uint4 v0 = pb[0];
        const uint4 v1 = pb[co1];
        const uint4 v2 = r1[0];
        const uint4 v3 = r1[co1];
        acc = hmax4(hmax4(v0, v1), hmax4(v2, v3));
    } else if (xlen <= 4 && ylen <= 4) {
        const int co2 = min(2, ym) * CS8;
        const int co3 = min(3, ym) * CS8;
        {
            const uint4* r0 = pb;
            const uint4* r1 = pb + (size_t)min(1, xm) * RS8;
            const uint4 a0 = r0[0], a1 = r0[co1], a2 = r0[co2], a3 = r0[co3];
            const uint4 b0 = r1[0], b1 = r1[co1], b2 = r1[co2], b3 = r1[co3];
            acc = hmax4(acc, hmax4(hmax4(a0, a1), hmax4(a2, a3)));
            acc = hmax4(acc, hmax4(hmax4(b0, b1), hmax4(b2, b3)));
        }
        {
            const uint4* r2 = pb + (size_t)min(2, xm) * RS8;
            const uint4* r3 = pb + (size_t)min(3, xm) * RS8;
            const uint4 a0 = r2[0], a1 = r2[co1], a2 = r2[co2], a3 = r2[co3];
            const uint4 b0 = r3[0], b1 = r3[co1], b2 = r3[co2], b3 = r3[co3];
            acc = hmax4(acc, hmax4(hmax4(a0, a1), hmax4(a2, a3)));
            acc = hmax4(acc, hmax4(hmax4(b0, b1), hmax4(b2, b3)));
        }
    } else {
        const int co2 = min(2, ym) * CS8;
        const int co3 = min(3, ym) * CS8;
        const int co4 = min(4, ym) * CS8;
        const int co5 = min(5, ym) * CS8;
        const uint4* rp = pb;
        for (int sx = 0; sx < xlen; ++sx) {
            const uint4 v0 = rp[0], v1 = rp[co1], v2 = rp[co2];
            const uint4 v3 = rp[co3], v4 = rp[co4], v5 = rp[co5];
            acc = hmax4(acc, hmax4(hmax4(v0, v1), hmax4(v2, hmax4(v3, hmax4(v4, v5)))));
            rp += RS8;
        }
        for (int sy = 6; sy < ylen; ++sy) {   // safety: ylen up to 10
            const uint4* p = pb + (size_t)sy * CS8;
            for (int sx = 0; sx < xlen; ++sx) {
                acc = hmax4(acc, p[0]);
                p += RS8;
            }
        }
    }

    // subnormal-hazard flag: any of this lane's 8 maxima with |v| < 1e-4
    const __half2 ab0 = __habs2(u2h(acc.x));
    const __half2 ab1 = __habs2(u2h(acc.y));
    const __half2 ab2 = __habs2(u2h(acc.z));
    const __half2 ab3 = __habs2(u2h(acc.w));
    const __half2 mn2 = __hmin2(__hmin2(ab0, ab1), __hmin2(ab2, ab3));
    const float2 mnf  = __half22float2(mn2);
    const bool small  = fminf(mnf.x, mnf.y) < 1e-4f;
    if (__ballot_sync(0xFFFFFFFFu, small)) {
        if (lane == 0) {
            const int pos = atomicAdd(&g_nflag, 1);
            g_flags[pos] = bin;
        }
    }

    const float2 f0 = __half22float2(u2h(acc.x));
    const float2 f1 = __half22float2(u2h(acc.y));
    const float2 f2 = __half22float2(u2h(acc.z));
    const float2 f3 = __half22float2(u2h(acc.w));
    float* op = out + (size_t)bin * C + lane * 8;
    *reinterpret_cast<float4*>(op)     = make_float4(f0.x, f0.y, f1.x, f1.y);
    *reinterpret_cast<float4*>(op + 4) = make_float4(f2.x, f2.y, f3.x, f3.y);
}

// K3: exact fp32 recompute of flagged bins (expected ~10 bins). Warp = entry.
__global__ __launch_bounds__(256) void fixup_kernel(
    const float* __restrict__ feat,
    const float* __restrict__ rois,
    float* __restrict__ out)
{
    const int n    = g_nflag;
    const int gw   = blockIdx.x * 8 + ((int)threadIdx.x >> 5);
    const int lane = (int)threadIdx.x & 31;

    for (int e = gw; e < n; e += 64 * 8) {
        const int bin = g_flags[e];
        const int r  = bin / (P * P);
        const int ij = bin - r * (P * P);
        const int i  = ij / P;
        const int j  = ij - i * P;

        int xs, xlen, ys, ylen;
        bin_bounds(__ldg(&rois[r * 4 + 0]), __ldg(&rois[r * 4 + 2]), i, xs, xlen);
        bin_bounds(__ldg(&rois[r * 4 + 1]), __ldg(&rois[r * 4 + 3]), j, ys, ylen);

        const float NEG = -INFINITY;
        float4 aL = make_float4(NEG, NEG, NEG, NEG);
        float4 aH = aL;
        const float* base = feat + (size_t)xs * FC + (size_t)ys * C + lane * 8;
        for (int sx = 0; sx < xlen; ++sx) {
            const float* p = base + (size_t)sx * FC;
            for (int sy = 0; sy < ylen; ++sy) {
                aL = fmax4f(aL, *reinterpret_cast<const float4*>(p));
                aH = fmax4f(aH, *reinterpret_cast<const float4*>(p + 4));
                p += C;
            }
        }
        float* op = out + (size_t)bin * C + lane * 8;
        *reinterpret_cast<float4*>(op)     = aL;
        *reinterpret_cast<float4*>(op + 4) = aH;
    }
}

extern "C" void kernel_launch(void* const* d_in, const int* in_sizes, int n_in,
                              void* d_out, int out_size) {
    const float* feat = (const float*)d_in[0];
    const float* rois = (const float*)d_in[1];
    if (n_in >= 2 && in_sizes[0] == NUM_ROIS * 4 && in_sizes[1] == H * W * C) {
        feat = (const float*)d_in[1];
        rois = (const float*)d_in[0];
    }
    float* out = (float*)d_out;

    convert_kernel<<<H * W * C / 8 / 256, 256>>>(feat);          // 512 blocks
    roi_pool_kernel<<<NBINS / 8, 256>>>(rois, out);              // 1568 blocks
    fixup_kernel<<<64, 256>>>(feat, rois, out);
}

// round 17
// speedup vs baseline: 1.2314x; 1.2314x over previous
#include <cuda_runtime.h>
#include <cuda_fp16.h>
#include <math.h>

#define H 64
#define W 64
#define C 256
#define P 7
#define NUM_ROIS 256
#define NBINS (NUM_ROIS * P * P)   // 12544
#define FC (W * C)                 // floats per x-row
#define RS8 (FC / 8)               // x-row stride in uint4 (8-half) units: 2048
#define CS8 (C / 8)                // y-col stride in uint4 units: 32

// fp16 feature map (2 MB), 16B-aligned via uint4
__device__ uint4 g_f16raw[H * W * C / 8];

__device__ __forceinline__ __half2 u2h(unsigned u) { return *reinterpret_cast<__half2*>(&u); }
__device__ __forceinline__ unsigned h2u(__half2 h) { return *reinterpret_cast<unsigned*>(&h); }
__device__ __forceinline__ unsigned hmax2u(unsigned a, unsigned b) {
    return h2u(__hmax2(u2h(a), u2h(b)));
}
__device__ __forceinline__ uint4 hmax4(uint4 a, uint4 b) {
    a.x = hmax2u(a.x, b.x); a.y = hmax2u(a.y, b.y);
    a.z = hmax2u(a.z, b.z); a.w = hmax2u(a.w, b.w);
    return a;
}
__device__ __forceinline__ float4 fmax4f(float4 a, float4 b) {
    a.x = fmaxf(a.x, b.x); a.y = fmaxf(a.y, b.y);
    a.z = fmaxf(a.z, b.z); a.w = fmaxf(a.w, b.w);
    return a;
}

// exact reference bin math
__device__ __forceinline__ void bin_bounds(float lo_f, float hi_f, int k,
                                           int& start, int& len) {
    const int lo   = (int)floorf(lo_f * 64.0f);
    const int hi   = (int)ceilf(hi_f * 64.0f);
    const int span = max(hi - lo, 1);
    int s          = lo + (k * span) / P;
    const int e    = lo + ((k + 1) * span + (P - 1)) / P;
    len = max(e - s, 1);
    start = min(max(s, 0), 63);
}

// K1: fp32 -> fp16. 256 blocks x 256 thr; each thread: 4 independent
// LDG.128 -> 2 uint4 stores (high MLP for the cold DRAM read).
__global__ __launch_bounds__(256) void convert_kernel(const float* __restrict__ feat) {
    const int t = blockIdx.x * 256 + (int)threadIdx.x;   // [0, 65536)
    const float4* f4 = reinterpret_cast<const float4*>(feat);
    const float4 a = f4[t * 4 + 0];
    const float4 b = f4[t * 4 + 1];
    const float4 c = f4[t * 4 + 2];
    const float4 d = f4[t * 4 + 3];
    uint4 o0, o1;
    o0.x = h2u(__floats2half2_rn(a.x, a.y));
    o0.y = h2u(__floats2half2_rn(a.z, a.w));
    o0.z = h2u(__floats2half2_rn(b.x, b.y));
    o0.w = h2u(__floats2half2_rn(b.z, b.w));
    o1.x = h2u(__floats2half2_rn(c.x, c.y));
    o1.y = h2u(__floats2half2_rn(c.z, c.w));
    o1.z = h2u(__floats2half2_rn(d.x, d.y));
    o1.w = h2u(__floats2half2_rn(d.z, d.w));
    g_f16raw[t * 2 + 0] = o0;
    g_f16raw[t * 2 + 1] = o1;
}

// K2: pool. 1568 CTAs x 256 thr = 8 warps; warp = one bin.
// Lane covers channels [8*lane, 8*lane+8): ONE 16B load per tap covers all C.
// Tap grids (batched; clamp-dups are same-address L1 hits, max-safe).
// Inline exact-fp32 recompute for warps with any |max| < 1e-4 (fp16
// subnormal hazard; ~1e-3 of bins).
__global__ __launch_bounds__(256) void roi_pool_kernel(
    const float* __restrict__ feat,   // fp32 original (fixup path only)
    const float* __restrict__ rois,
    float* __restrict__ out)          // (NBINS, C)
{
    const int bin  = blockIdx.x * 8 + ((int)threadIdx.x >> 5);
    const int lane = (int)threadIdx.x & 31;

    const int r  = bin / (P * P);
    const int ij = bin - r * (P * P);
    const int i  = ij / P;
    const int j  = ij - i * P;

    int xs, xlen, ys, ylen;
    bin_bounds(__ldg(&rois[r * 4 + 0]), __ldg(&rois[r * 4 + 2]), i, xs, xlen);
    bin_bounds(__ldg(&rois[r * 4 + 1]), __ldg(&rois[r * 4 + 3]), j, ys, ylen);

    const int xm = xlen - 1;
    const int ym = ylen - 1;
    const uint4* pb = g_f16raw + (size_t)xs * RS8 + (size_t)ys * CS8 + lane;
    const int co1 = min(1, ym) * CS8;

    const unsigned NEGU = 0xFC00FC00u;   // half2(-inf, -inf)
    uint4 acc = make_uint4(NEGU, NEGU, NEGU, NEGU);

    if (xlen <= 2 && ylen <= 2) {
        const uint4* r1 = pb + (size_t)min(1, xm) * RS8;
        const uint4 v0 = pb[0];
        const uint4 v1 = pb[co1];
        const uint4 v2 = r1[0];
        const uint4 v3 = r1[co1];
        acc = hmax4(hmax4(v0, v1), hmax4(v2, v3));
    } else if (xlen <= 4 && ylen <= 4) {
        const int co2 = min(2, ym) * CS8;
        const int co3 = min(3, ym) * CS8;
        {
            const uint4* r0 = pb;
            const uint4* r1 = pb + (size_t)min(1, xm) * RS8;
            const uint4 a0 = r0[0], a1 = r0[co1], a2 = r0[co2], a3 = r0[co3];
            const uint4 b0 = r1[0], b1 = r1[co1], b2 = r1[co2], b3 = r1[co3];
            acc = hmax4(acc, hmax4(hmax4(a0, a1), hmax4(a2, a3)));
            acc = hmax4(acc, hmax4(hmax4(b0, b1), hmax4(b2, b3)));
        }
        {
            const uint4* r2 = pb + (size_t)min(2, xm) * RS8;
            const uint4* r3 = pb + (size_t)min(3, xm) * RS8;
            const uint4 a0 = r2[0], a1 = r2[co1], a2 = r2[co2], a3 = r2[co3];
            const uint4 b0 = r3[0], b1 = r3[co1], b2 = r3[co2], b3 = r3[co3];
            acc = hmax4(acc, hmax4(hmax4(a0, a1), hmax4(a2, a3)));
            acc = hmax4(acc, hmax4(hmax4(b0, b1), hmax4(b2, b3)));
        }
    } else {
        const int co2 = min(2, ym) * CS8;
        const int co3 = min(3, ym) * CS8;
        const int co4 = min(4, ym) * CS8;
        const int co5 = min(5, ym) * CS8;
        const uint4* rp = pb;
        for (int sx = 0; sx < xlen; ++sx) {
            const uint4 v0 = rp[0], v1 = rp[co1], v2 = rp[co2];
            const uint4 v3 = rp[co3], v4 = rp[co4], v5 = rp[co5];
            acc = hmax4(acc, hmax4(hmax4(v0, v1), hmax4(v2, hmax4(v3, hmax4(v4, v5)))));
            rp += RS8;
        }
        for (int sy = 6; sy < ylen; ++sy) {   // safety (ylen>6 unexpected)
            const uint4* p = pb + (size_t)sy * CS8;
            for (int sx = 0; sx < xlen; ++sx) {
                acc = hmax4(acc, p[0]);
                p += RS8;
            }
        }
    }

    // subnormal hazard: any |max| < 1e-4 in this warp -> exact fp32 redo
    const __half2 ab0 = __habs2(u2h(acc.x));
    const __half2 ab1 = __habs2(u2h(acc.y));
    const __half2 ab2 = __habs2(u2h(acc.z));
    const __half2 ab3 = __habs2(u2h(acc.w));
    const __half2 mn2 = __hmin2(__hmin2(ab0, ab1), __hmin2(ab2, ab3));
    const float2 mnf  = __half22float2(mn2);
    const bool small  = fminf(mnf.x, mnf.y) < 1e-4f;

    float* op = out + (size_t)bin * C + lane * 8;

    if (__ballot_sync(0xFFFFFFFFu, small)) {
        // rare path (~10 warps of 12544): recompute bin exactly in fp32
        const float NEG = -INFINITY;
        float4 aL = make_float4(NEG, NEG, NEG, NEG);
        float4 aH = aL;
        const float* base = feat + (size_t)xs * FC + (size_t)ys * C + lane * 8;
        for (int sx = 0; sx < xlen; ++sx) {
            const float* p = base + (size_t)sx * FC;
            for (int sy = 0; sy < ylen; ++sy) {
                aL = fmax4f(aL, *reinterpret_cast<const float4*>(p));
                aH = fmax4f(aH, *reinterpret_cast<const float4*>(p + 4));
                p += C;
            }
        }
        *reinterpret_cast<float4*>(op)     = aL;
        *reinterpret_cast<float4*>(op + 4) = aH;
        return;
    }

    const float2 f0 = __half22float2(u2h(acc.x));
    const float2 f1 = __half22float2(u2h(acc.y));
    const float2 f2 = __half22float2(u2h(acc.z));
    const float2 f3 = __half22float2(u2h(acc.w));
    *reinterpret_cast<float4*>(op)     = make_float4(f0.x, f0.y, f1.x, f1.y);
    *reinterpret_cast<float4*>(op + 4) = make_float4(f2.x, f2.y, f3.x, f3.y);
}

extern "C" void kernel_launch(void* const* d_in, const int* in_sizes, int n_in,
                              void* d_out, int out_size) {
    const float* feat = (const float*)d_in[0];
    const float* rois = (const float*)d_in[1];
    if (n_in >= 2 && in_sizes[0] == NUM_ROIS * 4 && in_sizes[1] == H * W * C) {
        feat = (const float*)d_in[1];
        rois = (const float*)d_in[0];
    }
    float* out = (float*)d_out;

    convert_kernel<<<256, 256>>>(feat);           // 65536 thr x 4 LDG.128
    roi_pool_kernel<<<NBINS / 8, 256>>>(feat, rois, out);
}